// round 13
// baseline (speedup 1.0000x reference)
#include <cuda_runtime.h>
#include <cuda_bf16.h>
#include <math.h>

// Problem constants (fixed by the dataset)
#define BB   64
#define HH   1024
#define VV   32000
#define DEPTHN 5
#define LEAVES 32            // 2^DEPTH
#define MAXROWS (BB*LEAVES)  // 2048
#define GH_LD (6*HH)         // 6144 : [l gates 3H | r gates 3H]

// logits GEMM tiling (mma.sync, fat warp tiles)
#define LBM 128
#define LBN 256
#define LBK 64
#define LNSTG 3
#define NYB  (VV/LBN)        // 125 col-tiles
#define LKSTB 144            // padded smem row stride (bytes)
#define LA_STG (LBM*LKSTB)   // 18432
#define LB_STG (LBN*LKSTB)   // 36864
#define L_SMEM (LNSTG*(LA_STG+LB_STG))   // 165888

// ---------------- device scratch (static, no runtime alloc) ----------------
__device__ __align__(128) float            g_curA[MAXROWS*HH];
__device__ __align__(128) float            g_curB[MAXROWS*HH];
__device__ __align__(128) __nv_bfloat16    g_curbf[MAXROWS*HH];
__device__ __align__(128) float            g_gh[(MAXROWS/2)*GH_LD];
__device__ __align__(128) __nv_bfloat16    g_wcat[GH_LD*HH];
__device__ __align__(128) __nv_bfloat16    g_wout[(size_t)VV*HH];
__device__ float            g_lse[MAXROWS];
__device__ float            g_pmax[MAXROWS*NYB];
__device__ float            g_psum[MAXROWS*NYB];

// ---------------- helpers ----------------
__device__ __forceinline__ float sigmoidf_(float x) { return 1.f / (1.f + __expf(-x)); }

__device__ __forceinline__ void mma16816(float* c, const unsigned* a, const unsigned* b) {
    asm volatile(
        "mma.sync.aligned.m16n8k16.row.col.f32.bf16.bf16.f32 "
        "{%0,%1,%2,%3}, {%4,%5,%6,%7}, {%8,%9}, {%0,%1,%2,%3};\n"
        : "+f"(c[0]), "+f"(c[1]), "+f"(c[2]), "+f"(c[3])
        : "r"(a[0]), "r"(a[1]), "r"(a[2]), "r"(a[3]), "r"(b[0]), "r"(b[1]));
}

__device__ __forceinline__ void ldsm_x4(unsigned& r0, unsigned& r1, unsigned& r2, unsigned& r3,
                                        unsigned addr) {
    asm volatile("ldmatrix.sync.aligned.m8n8.x4.shared.b16 {%0,%1,%2,%3}, [%4];\n"
                 : "=r"(r0), "=r"(r1), "=r"(r2), "=r"(r3) : "r"(addr));
}

__device__ __forceinline__ void cp16(unsigned dst, const void* src, int szbytes) {
    asm volatile("cp.async.cg.shared.global [%0], [%1], 16, %2;\n"
                 :: "r"(dst), "l"(src), "r"(szbytes));
}
#define CP_COMMIT() asm volatile("cp.async.commit_group;\n" ::: "memory")
#define CP_WAIT(n)  asm volatile("cp.async.wait_group %0;\n" :: "n"(n) : "memory")

__device__ __forceinline__ unsigned smem_u32(const void* p) {
    return (unsigned)__cvta_generic_to_shared(p);
}

// online (max, sumexp)
__device__ __forceinline__ void lse_upd(float& m, float& s, float x) {
    if (x > m) { s *= __expf(m - x); m = x; }
    s += __expf(x - m);
}
__device__ __forceinline__ void lse_comb(float& m, float& s, float m2, float s2) {
    float M = fmaxf(m, m2);
    float ns = 0.f;
    if (M > -INFINITY) ns = s * __expf(m - M) + s2 * __expf(m2 - M);
    m = M; s = ns;
}

// ---------------- fp32 -> bf16 conversion ----------------
__global__ void f2bf_kernel(const float* __restrict__ src, __nv_bfloat16* __restrict__ dst, int n2) {
    int i = blockIdx.x * blockDim.x + threadIdx.x;
    if (i < n2) {
        float2 v = reinterpret_cast<const float2*>(src)[i];
        reinterpret_cast<__nv_bfloat162*>(dst)[i] = __float22bfloat162_rn(v);
    }
}

// ---------------- init ----------------
__global__ void init_kernel(const float* __restrict__ enc, float* __restrict__ cur,
                            __nv_bfloat16* __restrict__ curbf) {
    int i = blockIdx.x * blockDim.x + threadIdx.x;
    float v = enc[i];
    cur[i]   = v;
    curbf[i] = __float2bfloat16(v);
}

// =======================================================================
// logits GEMM: C[2048,32000] = A[2048,1024] @ B[32000,1024]^T + bias
// CTA M128 x N256, 256 threads, warp grid 2x4, warp tile 64x64.
// 3-stage cp.async. Fused per-(row, col-block) LSE partials.
// =======================================================================
__device__ __forceinline__ void l_stage_load(const __nv_bfloat16* __restrict__ A,
                                             const __nv_bfloat16* __restrict__ Bp,
                                             unsigned aS, unsigned bS,
                                             int rowBase, int k0, int tid) {
    // A tile: 128x64 bf16 -> 1024 x 16B chunks, 4 per thread
    #pragma unroll
    for (int i = 0; i < 4; i++) {
        int c  = tid + i * 256;
        int r  = c >> 3;
        int cc = (c & 7) << 3;
        cp16(aS + r * LKSTB + cc * 2, A + (size_t)(rowBase + r) * HH + k0 + cc, 16);
    }
    // B tile: 256x64 -> 2048 chunks, 8 per thread
    #pragma unroll
    for (int i = 0; i < 8; i++) {
        int c  = tid + i * 256;
        int r  = c >> 3;
        int cc = (c & 7) << 3;
        cp16(bS + r * LKSTB + cc * 2, Bp + (size_t)r * HH + k0 + cc, 16);
    }
}

__global__ void __launch_bounds__(256, 1)
gemm_logits_big(const __nv_bfloat16* __restrict__ A,
                const __nv_bfloat16* __restrict__ B,
                float* __restrict__ C,
                const float* __restrict__ bias,
                float* __restrict__ pmax, float* __restrict__ psum)
{
    extern __shared__ char dynsm[];
    __shared__ float smx[LBM][4], sms[LBM][4];

    const int tid  = threadIdx.x;
    const int warp = tid >> 5;
    const int lane = tid & 31;
    const int wm   = warp >> 2;      // 0..1 (m, 64 rows each)
    const int wn   = warp & 3;       // 0..3 (n, 64 cols each)
    const int ti   = lane & 3;
    const int g    = lane >> 2;
    const int rowBase = blockIdx.x * LBM;
    const int colBase = blockIdx.y * LBN;

    const __nv_bfloat16* Bp = B + (size_t)colBase * HH;

    const unsigned aB0 = smem_u32(dynsm);
    const unsigned bB0 = aB0 + LNSTG * LA_STG;

    float acc[4][8][4];
    #pragma unroll
    for (int mt = 0; mt < 4; mt++)
        #pragma unroll
        for (int nt = 0; nt < 8; nt++)
            #pragma unroll
            for (int q = 0; q < 4; q++) acc[mt][nt][q] = 0.f;

    const int NK = HH / LBK;         // 16

    l_stage_load(A, Bp, aB0, bB0, rowBase, 0, tid);          CP_COMMIT();
    l_stage_load(A, Bp, aB0 + LA_STG, bB0 + LB_STG, rowBase, LBK, tid); CP_COMMIT();

    const int aRowSel = lane & 15;
    const int aColSel = (lane >> 4) << 3;
    const int bRowSel = (lane & 7) + (((lane >> 4) & 1) << 3);
    const int bColSel = ((lane >> 3) & 1) << 3;

    for (int it = 0; it < NK; it++) {
        if (it + 2 < NK) {
            int s = (it + 2) % LNSTG;
            l_stage_load(A, Bp, aB0 + s * LA_STG, bB0 + s * LB_STG, rowBase, (it + 2) * LBK, tid);
            CP_COMMIT();
            CP_WAIT(2);
        } else if (it + 1 < NK) {
            CP_WAIT(1);
        } else {
            CP_WAIT(0);
        }
        __syncthreads();

        const int s = it % LNSTG;
        const unsigned aS = aB0 + s * LA_STG;
        const unsigned bS = bB0 + s * LB_STG;

        #pragma unroll
        for (int kk = 0; kk < LBK; kk += 16) {
            unsigned a[4][4], b[8][2];
            #pragma unroll
            for (int mt = 0; mt < 4; mt++) {
                int row = wm * 64 + mt * 16 + aRowSel;
                ldsm_x4(a[mt][0], a[mt][1], a[mt][2], a[mt][3],
                        aS + row * LKSTB + (kk + aColSel) * 2);
            }
            #pragma unroll
            for (int p = 0; p < 4; p++) {
                int row = wn * 64 + p * 16 + bRowSel;
                unsigned r0, r1, r2, r3;
                ldsm_x4(r0, r1, r2, r3, bS + row * LKSTB + (kk + bColSel) * 2);
                b[2*p][0] = r0; b[2*p][1] = r1; b[2*p+1][0] = r2; b[2*p+1][1] = r3;
            }
            #pragma unroll
            for (int mt = 0; mt < 4; mt++)
                #pragma unroll
                for (int nt = 0; nt < 8; nt++)
                    mma16816(acc[mt][nt], a[mt], b[nt]);
        }
        __syncthreads();
    }

    // ---- epilogue: bias + store + LSE partials (all indices in-range: M=2048, N=32000 exact)
    float rm[4][2], rs[4][2];
    #pragma unroll
    for (int mt = 0; mt < 4; mt++)
        #pragma unroll
        for (int h = 0; h < 2; h++) { rm[mt][h] = -INFINITY; rs[mt][h] = 0.f; }

    #pragma unroll
    for (int mt = 0; mt < 4; mt++) {
        int r0 = rowBase + wm * 64 + mt * 16 + g;
        #pragma unroll
        for (int nt = 0; nt < 8; nt++) {
            int c = colBase + wn * 64 + nt * 8 + 2 * ti;
            float b0 = bias[c], b1 = bias[c + 1];
            float v0 = acc[mt][nt][0] + b0, v1 = acc[mt][nt][1] + b1;
            float v2 = acc[mt][nt][2] + b0, v3 = acc[mt][nt][3] + b1;
            C[(size_t)r0 * VV + c]           = v0;
            C[(size_t)r0 * VV + c + 1]       = v1;
            C[(size_t)(r0 + 8) * VV + c]     = v2;
            C[(size_t)(r0 + 8) * VV + c + 1] = v3;
            lse_upd(rm[mt][0], rs[mt][0], v0); lse_upd(rm[mt][0], rs[mt][0], v1);
            lse_upd(rm[mt][1], rs[mt][1], v2); lse_upd(rm[mt][1], rs[mt][1], v3);
        }
    }

    // reduce across ti (4 lanes share a row)
    #pragma unroll
    for (int mt = 0; mt < 4; mt++)
        #pragma unroll
        for (int h = 0; h < 2; h++) {
            #pragma unroll
            for (int o = 1; o <= 2; o <<= 1) {
                float om = __shfl_xor_sync(0xffffffffu, rm[mt][h], o);
                float os = __shfl_xor_sync(0xffffffffu, rs[mt][h], o);
                lse_comb(rm[mt][h], rs[mt][h], om, os);
            }
        }
    if (ti == 0) {
        #pragma unroll
        for (int mt = 0; mt < 4; mt++)
            #pragma unroll
            for (int h = 0; h < 2; h++) {
                int row = wm * 64 + mt * 16 + h * 8 + g;
                smx[row][wn] = rm[mt][h];
                sms[row][wn] = rs[mt][h];
            }
    }
    __syncthreads();
    if (tid < LBM) {
        float m = smx[tid][0], s = sms[tid][0];
        lse_comb(m, s, smx[tid][1], sms[tid][1]);
        lse_comb(m, s, smx[tid][2], sms[tid][2]);
        lse_comb(m, s, smx[tid][3], sms[tid][3]);
        int grow = rowBase + tid;
        pmax[(size_t)grow * NYB + blockIdx.y] = m;
        psum[(size_t)grow * NYB + blockIdx.y] = s;
    }
}

// =======================================================================
// mma.sync pipelined GEMM for the tree levels (proven R9 kernel)
// =======================================================================
#define BM 128
#define BN 128
#define BK 64
#define KSTB 144
#define STGB (BM*KSTB)
#define SMEM_BYTES (4*STGB)

__device__ __forceinline__ void stage_load(const __nv_bfloat16* __restrict__ A,
                                           const __nv_bfloat16* __restrict__ B,
                                           unsigned aS, unsigned bS,
                                           int rowBase, int M, int k0, int tid) {
    #pragma unroll
    for (int i = 0; i < 4; i++) {
        int c  = tid + i * 256;
        int r  = c >> 3;
        int cc = (c & 7) << 3;
        const __nv_bfloat16* src = A + (size_t)(rowBase + r) * HH + k0 + cc;
        int sz = (rowBase + r < M) ? 16 : 0;
        cp16(aS + r * KSTB + cc * 2, src, sz);
    }
    #pragma unroll
    for (int i = 0; i < 4; i++) {
        int c  = tid + i * 256;
        int r  = c >> 3;
        int cc = (c & 7) << 3;
        cp16(bS + r * KSTB + cc * 2, B + (size_t)r * HH + k0 + cc, 16);
    }
}

__global__ void __launch_bounds__(256, 2)
gemm_bf16_pipe(const __nv_bfloat16* __restrict__ A,
               const __nv_bfloat16* __restrict__ B,
               float* __restrict__ C,
               int M, int ldc)
{
    extern __shared__ char dynsm[];

    const int tid  = threadIdx.x;
    const int warp = tid >> 5;
    const int lane = tid & 31;
    const int wm   = warp >> 1;
    const int wn   = warp & 1;
    const int ti   = lane & 3;
    const int g    = lane >> 2;
    const int rowBase = blockIdx.x * BM;
    const int colBase = blockIdx.y * BN;

    const __nv_bfloat16* Bp = B + (size_t)colBase * HH;

    unsigned aB0 = smem_u32(dynsm);
    unsigned bB0 = aB0 + 2 * STGB;

    float acc[2][8][4];
    #pragma unroll
    for (int mt = 0; mt < 2; mt++)
        #pragma unroll
        for (int nt = 0; nt < 8; nt++)
            #pragma unroll
            for (int q = 0; q < 4; q++) acc[mt][nt][q] = 0.f;

    const int NK = HH / BK;

    stage_load(A, Bp, aB0, bB0, rowBase, M, 0, tid);
    CP_COMMIT();

    const int aRowSel = lane & 15;
    const int aColSel = (lane >> 4) << 3;
    const int bRowSel = (lane & 7) + (((lane >> 4) & 1) << 3);
    const int bColSel = ((lane >> 3) & 1) << 3;

    for (int it = 0; it < NK; it++) {
        if (it + 1 < NK) {
            int s = (it + 1) & 1;
            stage_load(A, Bp, aB0 + s * STGB, bB0 + s * STGB, rowBase, M, (it + 1) * BK, tid);
            CP_COMMIT();
            CP_WAIT(1);
        } else {
            CP_WAIT(0);
        }
        __syncthreads();

        const int s = it & 1;
        const unsigned aS = aB0 + s * STGB;
        const unsigned bS = bB0 + s * STGB;

        #pragma unroll
        for (int kk = 0; kk < BK; kk += 16) {
            unsigned a[2][4], b[8][2];
            #pragma unroll
            for (int mt = 0; mt < 2; mt++) {
                int row = wm * 32 + mt * 16 + aRowSel;
                ldsm_x4(a[mt][0], a[mt][1], a[mt][2], a[mt][3],
                        aS + row * KSTB + (kk + aColSel) * 2);
            }
            #pragma unroll
            for (int p = 0; p < 4; p++) {
                int row = wn * 64 + p * 16 + bRowSel;
                unsigned r0, r1, r2, r3;
                ldsm_x4(r0, r1, r2, r3, bS + row * KSTB + (kk + bColSel) * 2);
                b[2*p][0] = r0; b[2*p][1] = r1; b[2*p+1][0] = r2; b[2*p+1][1] = r3;
            }
            #pragma unroll
            for (int mt = 0; mt < 2; mt++)
                #pragma unroll
                for (int nt = 0; nt < 8; nt++)
                    mma16816(acc[mt][nt], a[mt], b[nt]);
        }
        __syncthreads();
    }

    #pragma unroll
    for (int mt = 0; mt < 2; mt++) {
        int r0 = rowBase + wm * 32 + mt * 16 + g;
        #pragma unroll
        for (int nt = 0; nt < 8; nt++) {
            int c = colBase + wn * 64 + nt * 8 + 2 * ti;
            if (r0 < M) {
                C[(size_t)r0 * ldc + c]     = acc[mt][nt][0];
                C[(size_t)r0 * ldc + c + 1] = acc[mt][nt][1];
            }
            if (r0 + 8 < M) {
                C[(size_t)(r0 + 8) * ldc + c]     = acc[mt][nt][2];
                C[(size_t)(r0 + 8) * ldc + c + 1] = acc[mt][nt][3];
            }
        }
    }
}

// ---------------- GRU gates ----------------
__global__ void gru_gate_kernel(const float* __restrict__ cur,
                                const float* __restrict__ gh,
                                const float* __restrict__ bih_l, const float* __restrict__ bhh_l,
                                const float* __restrict__ bih_r, const float* __restrict__ bhh_r,
                                float* __restrict__ nxt, __nv_bfloat16* __restrict__ nxtbf)
{
    int row = blockIdx.x;
    const float* gp = gh  + (size_t)row * GH_LD;
    const float* hp = cur + (size_t)row * HH;
    size_t lo = (size_t)(2 * row) * HH;

    for (int j = threadIdx.x; j < HH; j += blockDim.x) {
        float hv = hp[j];
        float g0 = gp[j], g1 = gp[HH + j], g2 = gp[2 * HH + j];
        float r  = sigmoidf_(bih_l[j]        + bhh_l[j]        + g0);
        float z  = sigmoidf_(bih_l[HH + j]   + bhh_l[HH + j]   + g1);
        float n  = tanhf   (bih_l[2*HH + j]  + r * (g2 + bhh_l[2*HH + j]));
        float left = (1.f - z) * n + z * hv;
        g0 = gp[3*HH + j]; g1 = gp[4*HH + j]; g2 = gp[5*HH + j];
        float r2 = sigmoidf_(bih_r[j]        + bhh_r[j]        + g0);
        float z2 = sigmoidf_(bih_r[HH + j]   + bhh_r[HH + j]   + g1);
        float n2 = tanhf   (bih_r[2*HH + j]  + r2 * (g2 + bhh_r[2*HH + j]));
        float right = (1.f - z2) * n2 + z2 * hv;

        nxt[lo + j]        = left;
        nxt[lo + HH + j]   = right;
        nxtbf[lo + j]      = __float2bfloat16(left);
        nxtbf[lo + HH + j] = __float2bfloat16(right);
    }
}

// ---------------- finish LSE from per-block partials ----------------
__global__ void lse_finish_kernel(const float* __restrict__ pmax, const float* __restrict__ psum,
                                  float* __restrict__ lse, int nyb) {
    int row = blockIdx.x;
    float m = -INFINITY, s = 0.f;
    for (int i = threadIdx.x; i < nyb; i += blockDim.x)
        lse_comb(m, s, pmax[(size_t)row * nyb + i], psum[(size_t)row * nyb + i]);
    __shared__ float sm[256], ss[256];
    sm[threadIdx.x] = m; ss[threadIdx.x] = s;
    __syncthreads();
    for (int o = 128; o > 0; o >>= 1) {
        if (threadIdx.x < o) {
            float mm = sm[threadIdx.x], sv = ss[threadIdx.x];
            lse_comb(mm, sv, sm[threadIdx.x + o], ss[threadIdx.x + o]);
            sm[threadIdx.x] = mm; ss[threadIdx.x] = sv;
        }
        __syncthreads();
    }
    if (threadIdx.x == 0) lse[row] = sm[0] + __logf(ss[0]);
}

__global__ void norm_kernel(float* __restrict__ logits, const float* __restrict__ lse) {
    int row = blockIdx.x;
    float l = lse[row];
    float4* p = reinterpret_cast<float4*>(logits + (size_t)row * VV);
    for (int i = threadIdx.x; i < VV / 4; i += blockDim.x) {
        float4 v = p[i];
        v.x -= l; v.y -= l; v.z -= l; v.w -= l;
        p[i] = v;
    }
}

// ---------------- launch ----------------
extern "C" void kernel_launch(void* const* d_in, const int* in_sizes, int n_in,
                              void* d_out, int out_size) {
    const float* enc   = (const float*)d_in[0];
    const float* Whh_l = (const float*)d_in[1];
    const float* bih_l = (const float*)d_in[2];
    const float* bhh_l = (const float*)d_in[3];
    const float* Whh_r = (const float*)d_in[4];
    const float* bih_r = (const float*)d_in[5];
    const float* bhh_r = (const float*)d_in[6];
    const float* W_out = (const float*)d_in[7];
    const float* b_out = (const float*)d_in[8];
    float* out = (float*)d_out;

    float *p_curA, *p_curB, *p_gh, *p_lse, *p_pmax, *p_psum;
    __nv_bfloat16 *p_curbf, *p_wcat, *p_wout;
    cudaGetSymbolAddress((void**)&p_curA,  g_curA);
    cudaGetSymbolAddress((void**)&p_curB,  g_curB);
    cudaGetSymbolAddress((void**)&p_gh,    g_gh);
    cudaGetSymbolAddress((void**)&p_lse,   g_lse);
    cudaGetSymbolAddress((void**)&p_pmax,  g_pmax);
    cudaGetSymbolAddress((void**)&p_psum,  g_psum);
    cudaGetSymbolAddress((void**)&p_curbf, g_curbf);
    cudaGetSymbolAddress((void**)&p_wcat,  g_wcat);
    cudaGetSymbolAddress((void**)&p_wout,  g_wout);

    cudaFuncSetAttribute(gemm_bf16_pipe,  cudaFuncAttributeMaxDynamicSharedMemorySize, SMEM_BYTES);
    cudaFuncSetAttribute(gemm_logits_big, cudaFuncAttributeMaxDynamicSharedMemorySize, L_SMEM);

    // weight conversions (every call — deterministic)
    {
        int nW = 3 * HH * HH;
        int n2 = nW / 2;
        f2bf_kernel<<<(n2 + 255) / 256, 256>>>(Whh_l, p_wcat, n2);
        f2bf_kernel<<<(n2 + 255) / 256, 256>>>(Whh_r, p_wcat + nW, n2);
        int n2o = (VV * HH) / 2;
        f2bf_kernel<<<(n2o + 255) / 256, 256>>>(W_out, p_wout, n2o);
    }

    // level 0 input
    init_kernel<<<(BB * HH) / 256, 256>>>(enc, p_curA, p_curbf);

    // tree expansion (proven mma.sync path)
    float* cur = p_curA;
    float* nxt = p_curB;
    for (int level = 0; level < DEPTHN; level++) {
        int rows = BB << level;                               // 64..1024
        dim3 grid((rows + BM - 1) / BM, GH_LD / BN);
        gemm_bf16_pipe<<<grid, 256, SMEM_BYTES>>>(p_curbf, p_wcat, p_gh, rows, GH_LD);
        gru_gate_kernel<<<rows, 256>>>(cur, p_gh, bih_l, bhh_l, bih_r, bhh_r, nxt, p_curbf);
        float* t = cur; cur = nxt; nxt = t;
    }

    // output projection with fused LSE partials
    {
        dim3 grid(MAXROWS / LBM, VV / LBN);                   // (16, 125)
        gemm_logits_big<<<grid, 256, L_SMEM>>>(p_curbf, p_wout, out, b_out, p_pmax, p_psum);
    }

    // log_softmax finish
    lse_finish_kernel<<<MAXROWS, 256>>>(p_pmax, p_psum, p_lse, NYB);
    norm_kernel<<<MAXROWS, 256>>>(out, p_lse);
}

// round 14
// speedup vs baseline: 1.1092x; 1.1092x over previous
#include <cuda_runtime.h>
#include <cuda_bf16.h>
#include <math.h>

// Problem constants (fixed by the dataset)
#define BB   64
#define HH   1024
#define VV   32000
#define DEPTHN 5
#define LEAVES 32            // 2^DEPTH
#define MAXROWS (BB*LEAVES)  // 2048
#define GH_LD (6*HH)         // 6144 : [l gates 3H | r gates 3H]

// logits GEMM: CTA 128x128x64, 128 threads, warp grid 2x2, warp tile 64x64
#define LBM 128
#define LBN 128
#define LBK 64
#define NYB  (VV/LBN)        // 250 col-tiles
#define LKSTB 144            // padded smem row stride (bytes)
#define LSTG (LBM*LKSTB)     // 18432 per tile per stage
#define L_SMEM (4*LSTG)      // 2 stages x (A+B) = 73728

// ---------------- device scratch (static, no runtime alloc) ----------------
__device__ __align__(128) float            g_curA[MAXROWS*HH];
__device__ __align__(128) float            g_curB[MAXROWS*HH];
__device__ __align__(128) __nv_bfloat16    g_curbf[MAXROWS*HH];
__device__ __align__(128) float            g_gh[(MAXROWS/2)*GH_LD];
__device__ __align__(128) __nv_bfloat16    g_wcat[GH_LD*HH];
__device__ __align__(128) __nv_bfloat16    g_wout[(size_t)VV*HH];
__device__ float            g_pmax[MAXROWS*NYB];
__device__ float            g_psum[MAXROWS*NYB];

// ---------------- helpers ----------------
__device__ __forceinline__ float sigmoidf_(float x) { return 1.f / (1.f + __expf(-x)); }

__device__ __forceinline__ void mma16816(float* c, const unsigned* a, const unsigned* b) {
    asm volatile(
        "mma.sync.aligned.m16n8k16.row.col.f32.bf16.bf16.f32 "
        "{%0,%1,%2,%3}, {%4,%5,%6,%7}, {%8,%9}, {%0,%1,%2,%3};\n"
        : "+f"(c[0]), "+f"(c[1]), "+f"(c[2]), "+f"(c[3])
        : "r"(a[0]), "r"(a[1]), "r"(a[2]), "r"(a[3]), "r"(b[0]), "r"(b[1]));
}

__device__ __forceinline__ void ldsm_x4(unsigned& r0, unsigned& r1, unsigned& r2, unsigned& r3,
                                        unsigned addr) {
    asm volatile("ldmatrix.sync.aligned.m8n8.x4.shared.b16 {%0,%1,%2,%3}, [%4];\n"
                 : "=r"(r0), "=r"(r1), "=r"(r2), "=r"(r3) : "r"(addr));
}

__device__ __forceinline__ void cp16(unsigned dst, const void* src, int szbytes) {
    asm volatile("cp.async.cg.shared.global [%0], [%1], 16, %2;\n"
                 :: "r"(dst), "l"(src), "r"(szbytes));
}
#define CP_COMMIT() asm volatile("cp.async.commit_group;\n" ::: "memory")
#define CP_WAIT(n)  asm volatile("cp.async.wait_group %0;\n" :: "n"(n) : "memory")

__device__ __forceinline__ unsigned smem_u32(const void* p) {
    return (unsigned)__cvta_generic_to_shared(p);
}

// online (max, sumexp)
__device__ __forceinline__ void lse_upd(float& m, float& s, float x) {
    if (x > m) { s *= __expf(m - x); m = x; }
    s += __expf(x - m);
}
__device__ __forceinline__ void lse_comb(float& m, float& s, float m2, float s2) {
    float M = fmaxf(m, m2);
    float ns = 0.f;
    if (M > -INFINITY) ns = s * __expf(m - M) + s2 * __expf(m2 - M);
    m = M; s = ns;
}

// ---------------- fp32 -> bf16 conversion ----------------
__global__ void f2bf_kernel(const float* __restrict__ src, __nv_bfloat16* __restrict__ dst, int n2) {
    int i = blockIdx.x * blockDim.x + threadIdx.x;
    if (i < n2) {
        float2 v = reinterpret_cast<const float2*>(src)[i];
        reinterpret_cast<__nv_bfloat162*>(dst)[i] = __float22bfloat162_rn(v);
    }
}

// ---------------- init ----------------
__global__ void init_kernel(const float* __restrict__ enc, float* __restrict__ cur,
                            __nv_bfloat16* __restrict__ curbf) {
    int i = blockIdx.x * blockDim.x + threadIdx.x;
    float v = enc[i];
    cur[i]   = v;
    curbf[i] = __float2bfloat16(v);
}

// =======================================================================
// logits GEMM: C[2048,32000] = A[2048,1024] @ B[32000,1024]^T + bias
// CTA 128x128x64, 128 threads (4 warps, 2x2), warp tile 64x64.
// 2-stage cp.async, 2 CTAs/SM. Fused per-(row, col-block) LSE partials.
// =======================================================================
__device__ __forceinline__ void l_stage_load(const __nv_bfloat16* __restrict__ A,
                                             const __nv_bfloat16* __restrict__ Bp,
                                             unsigned aS, unsigned bS,
                                             int rowBase, int k0, int tid) {
    // A tile: 128 rows x 64 bf16 = 1024 x 16B chunks, 8 per thread
    #pragma unroll
    for (int i = 0; i < 8; i++) {
        int c  = tid + i * 128;
        int r  = c >> 3;
        int cc = (c & 7) << 3;
        cp16(aS + r * LKSTB + cc * 2, A + (size_t)(rowBase + r) * HH + k0 + cc, 16);
    }
    // B tile: 128 rows x 64 bf16
    #pragma unroll
    for (int i = 0; i < 8; i++) {
        int c  = tid + i * 128;
        int r  = c >> 3;
        int cc = (c & 7) << 3;
        cp16(bS + r * LKSTB + cc * 2, Bp + (size_t)r * HH + k0 + cc, 16);
    }
}

__global__ void __launch_bounds__(128, 2)
gemm_logits(const __nv_bfloat16* __restrict__ A,
            const __nv_bfloat16* __restrict__ B,
            float* __restrict__ C,
            const float* __restrict__ bias,
            float* __restrict__ pmax, float* __restrict__ psum)
{
    extern __shared__ char dynsm[];
    __shared__ float smx[LBM][2], sms[LBM][2];

    const int tid  = threadIdx.x;
    const int warp = tid >> 5;
    const int lane = tid & 31;
    const int wm   = warp >> 1;      // 0..1 (64 rows each)
    const int wn   = warp & 1;       // 0..1 (64 cols each)
    const int ti   = lane & 3;
    const int g    = lane >> 2;
    const int rowBase = blockIdx.x * LBM;
    const int colBase = blockIdx.y * LBN;

    const __nv_bfloat16* Bp = B + (size_t)colBase * HH;

    const unsigned aB0 = smem_u32(dynsm);
    const unsigned bB0 = aB0 + 2 * LSTG;

    float acc[4][8][4];
    #pragma unroll
    for (int mt = 0; mt < 4; mt++)
        #pragma unroll
        for (int nt = 0; nt < 8; nt++)
            #pragma unroll
            for (int q = 0; q < 4; q++) acc[mt][nt][q] = 0.f;

    const int NK = HH / LBK;         // 16

    l_stage_load(A, Bp, aB0, bB0, rowBase, 0, tid);
    CP_COMMIT();

    const int aRowSel = lane & 15;
    const int aColSel = (lane >> 4) << 3;
    const int bRowSel = (lane & 7) + (((lane >> 4) & 1) << 3);
    const int bColSel = ((lane >> 3) & 1) << 3;

    for (int it = 0; it < NK; it++) {
        if (it + 1 < NK) {
            int s = (it + 1) & 1;
            l_stage_load(A, Bp, aB0 + s * LSTG, bB0 + s * LSTG, rowBase, (it + 1) * LBK, tid);
            CP_COMMIT();
            CP_WAIT(1);
        } else {
            CP_WAIT(0);
        }
        __syncthreads();

        const int s = it & 1;
        const unsigned aS = aB0 + s * LSTG;
        const unsigned bS = bB0 + s * LSTG;

        #pragma unroll
        for (int kk = 0; kk < LBK; kk += 16) {
            unsigned a[4][4], b[8][2];
            #pragma unroll
            for (int mt = 0; mt < 4; mt++) {
                int row = wm * 64 + mt * 16 + aRowSel;
                ldsm_x4(a[mt][0], a[mt][1], a[mt][2], a[mt][3],
                        aS + row * LKSTB + (kk + aColSel) * 2);
            }
            #pragma unroll
            for (int p = 0; p < 4; p++) {
                int row = wn * 64 + p * 16 + bRowSel;
                unsigned r0, r1, r2, r3;
                ldsm_x4(r0, r1, r2, r3, bS + row * LKSTB + (kk + bColSel) * 2);
                b[2*p][0] = r0; b[2*p][1] = r1; b[2*p+1][0] = r2; b[2*p+1][1] = r3;
            }
            #pragma unroll
            for (int mt = 0; mt < 4; mt++)
                #pragma unroll
                for (int nt = 0; nt < 8; nt++)
                    mma16816(acc[mt][nt], a[mt], b[nt]);
        }
        __syncthreads();
    }

    // ---- epilogue: bias + store + LSE partials (M=2048, N=32000 exact multiples)
    float rm[4][2], rs[4][2];
    #pragma unroll
    for (int mt = 0; mt < 4; mt++)
        #pragma unroll
        for (int h = 0; h < 2; h++) { rm[mt][h] = -INFINITY; rs[mt][h] = 0.f; }

    #pragma unroll
    for (int mt = 0; mt < 4; mt++) {
        int r0 = rowBase + wm * 64 + mt * 16 + g;
        #pragma unroll
        for (int nt = 0; nt < 8; nt++) {
            int c = colBase + wn * 64 + nt * 8 + 2 * ti;
            float b0 = bias[c], b1 = bias[c + 1];
            float v0 = acc[mt][nt][0] + b0, v1 = acc[mt][nt][1] + b1;
            float v2 = acc[mt][nt][2] + b0, v3 = acc[mt][nt][3] + b1;
            C[(size_t)r0 * VV + c]           = v0;
            C[(size_t)r0 * VV + c + 1]       = v1;
            C[(size_t)(r0 + 8) * VV + c]     = v2;
            C[(size_t)(r0 + 8) * VV + c + 1] = v3;
            lse_upd(rm[mt][0], rs[mt][0], v0); lse_upd(rm[mt][0], rs[mt][0], v1);
            lse_upd(rm[mt][1], rs[mt][1], v2); lse_upd(rm[mt][1], rs[mt][1], v3);
        }
    }

    // reduce across ti (4 lanes share a row)
    #pragma unroll
    for (int mt = 0; mt < 4; mt++)
        #pragma unroll
        for (int h = 0; h < 2; h++) {
            #pragma unroll
            for (int o = 1; o <= 2; o <<= 1) {
                float om = __shfl_xor_sync(0xffffffffu, rm[mt][h], o);
                float os = __shfl_xor_sync(0xffffffffu, rs[mt][h], o);
                lse_comb(rm[mt][h], rs[mt][h], om, os);
            }
        }
    if (ti == 0) {
        #pragma unroll
        for (int mt = 0; mt < 4; mt++)
            #pragma unroll
            for (int h = 0; h < 2; h++) {
                int row = wm * 64 + mt * 16 + h * 8 + g;
                smx[row][wn] = rm[mt][h];
                sms[row][wn] = rs[mt][h];
            }
    }
    __syncthreads();
    // 128 threads == LBM rows
    {
        float m = smx[tid][0], s = sms[tid][0];
        lse_comb(m, s, smx[tid][1], sms[tid][1]);
        int grow = rowBase + tid;
        pmax[(size_t)grow * NYB + blockIdx.y] = m;
        psum[(size_t)grow * NYB + blockIdx.y] = s;
    }
}

// =======================================================================
// mma.sync pipelined GEMM for the tree levels (proven R9 kernel)
// =======================================================================
#define BM 128
#define BN 128
#define BK 64
#define KSTB 144
#define STGB (BM*KSTB)
#define SMEM_BYTES (4*STGB)

__device__ __forceinline__ void stage_load(const __nv_bfloat16* __restrict__ A,
                                           const __nv_bfloat16* __restrict__ B,
                                           unsigned aS, unsigned bS,
                                           int rowBase, int M, int k0, int tid) {
    #pragma unroll
    for (int i = 0; i < 4; i++) {
        int c  = tid + i * 256;
        int r  = c >> 3;
        int cc = (c & 7) << 3;
        const __nv_bfloat16* src = A + (size_t)(rowBase + r) * HH + k0 + cc;
        int sz = (rowBase + r < M) ? 16 : 0;
        cp16(aS + r * KSTB + cc * 2, src, sz);
    }
    #pragma unroll
    for (int i = 0; i < 4; i++) {
        int c  = tid + i * 256;
        int r  = c >> 3;
        int cc = (c & 7) << 3;
        cp16(bS + r * KSTB + cc * 2, B + (size_t)r * HH + k0 + cc, 16);
    }
}

__global__ void __launch_bounds__(256, 2)
gemm_bf16_pipe(const __nv_bfloat16* __restrict__ A,
               const __nv_bfloat16* __restrict__ B,
               float* __restrict__ C,
               int M, int ldc)
{
    extern __shared__ char dynsm[];

    const int tid  = threadIdx.x;
    const int warp = tid >> 5;
    const int lane = tid & 31;
    const int wm   = warp >> 1;
    const int wn   = warp & 1;
    const int ti   = lane & 3;
    const int g    = lane >> 2;
    const int rowBase = blockIdx.x * BM;
    const int colBase = blockIdx.y * BN;

    const __nv_bfloat16* Bp = B + (size_t)colBase * HH;

    unsigned aB0 = smem_u32(dynsm);
    unsigned bB0 = aB0 + 2 * STGB;

    float acc[2][8][4];
    #pragma unroll
    for (int mt = 0; mt < 2; mt++)
        #pragma unroll
        for (int nt = 0; nt < 8; nt++)
            #pragma unroll
            for (int q = 0; q < 4; q++) acc[mt][nt][q] = 0.f;

    const int NK = HH / BK;

    stage_load(A, Bp, aB0, bB0, rowBase, M, 0, tid);
    CP_COMMIT();

    const int aRowSel = lane & 15;
    const int aColSel = (lane >> 4) << 3;
    const int bRowSel = (lane & 7) + (((lane >> 4) & 1) << 3);
    const int bColSel = ((lane >> 3) & 1) << 3;

    for (int it = 0; it < NK; it++) {
        if (it + 1 < NK) {
            int s = (it + 1) & 1;
            stage_load(A, Bp, aB0 + s * STGB, bB0 + s * STGB, rowBase, M, (it + 1) * BK, tid);
            CP_COMMIT();
            CP_WAIT(1);
        } else {
            CP_WAIT(0);
        }
        __syncthreads();

        const int s = it & 1;
        const unsigned aS = aB0 + s * STGB;
        const unsigned bS = bB0 + s * STGB;

        #pragma unroll
        for (int kk = 0; kk < BK; kk += 16) {
            unsigned a[2][4], b[8][2];
            #pragma unroll
            for (int mt = 0; mt < 2; mt++) {
                int row = wm * 32 + mt * 16 + aRowSel;
                ldsm_x4(a[mt][0], a[mt][1], a[mt][2], a[mt][3],
                        aS + row * KSTB + (kk + aColSel) * 2);
            }
            #pragma unroll
            for (int p = 0; p < 4; p++) {
                int row = wn * 64 + p * 16 + bRowSel;
                unsigned r0, r1, r2, r3;
                ldsm_x4(r0, r1, r2, r3, bS + row * KSTB + (kk + bColSel) * 2);
                b[2*p][0] = r0; b[2*p][1] = r1; b[2*p+1][0] = r2; b[2*p+1][1] = r3;
            }
            #pragma unroll
            for (int mt = 0; mt < 2; mt++)
                #pragma unroll
                for (int nt = 0; nt < 8; nt++)
                    mma16816(acc[mt][nt], a[mt], b[nt]);
        }
        __syncthreads();
    }

    #pragma unroll
    for (int mt = 0; mt < 2; mt++) {
        int r0 = rowBase + wm * 32 + mt * 16 + g;
        #pragma unroll
        for (int nt = 0; nt < 8; nt++) {
            int c = colBase + wn * 64 + nt * 8 + 2 * ti;
            if (r0 < M) {
                C[(size_t)r0 * ldc + c]     = acc[mt][nt][0];
                C[(size_t)r0 * ldc + c + 1] = acc[mt][nt][1];
            }
            if (r0 + 8 < M) {
                C[(size_t)(r0 + 8) * ldc + c]     = acc[mt][nt][2];
                C[(size_t)(r0 + 8) * ldc + c + 1] = acc[mt][nt][3];
            }
        }
    }
}

// ---------------- GRU gates ----------------
__global__ void gru_gate_kernel(const float* __restrict__ cur,
                                const float* __restrict__ gh,
                                const float* __restrict__ bih_l, const float* __restrict__ bhh_l,
                                const float* __restrict__ bih_r, const float* __restrict__ bhh_r,
                                float* __restrict__ nxt, __nv_bfloat16* __restrict__ nxtbf)
{
    int row = blockIdx.x;
    const float* gp = gh  + (size_t)row * GH_LD;
    const float* hp = cur + (size_t)row * HH;
    size_t lo = (size_t)(2 * row) * HH;

    for (int j = threadIdx.x; j < HH; j += blockDim.x) {
        float hv = hp[j];
        float g0 = gp[j], g1 = gp[HH + j], g2 = gp[2 * HH + j];
        float r  = sigmoidf_(bih_l[j]        + bhh_l[j]        + g0);
        float z  = sigmoidf_(bih_l[HH + j]   + bhh_l[HH + j]   + g1);
        float n  = tanhf   (bih_l[2*HH + j]  + r * (g2 + bhh_l[2*HH + j]));
        float left = (1.f - z) * n + z * hv;
        g0 = gp[3*HH + j]; g1 = gp[4*HH + j]; g2 = gp[5*HH + j];
        float r2 = sigmoidf_(bih_r[j]        + bhh_r[j]        + g0);
        float z2 = sigmoidf_(bih_r[HH + j]   + bhh_r[HH + j]   + g1);
        float n2 = tanhf   (bih_r[2*HH + j]  + r2 * (g2 + bhh_r[2*HH + j]));
        float right = (1.f - z2) * n2 + z2 * hv;

        nxt[lo + j]        = left;
        nxt[lo + HH + j]   = right;
        nxtbf[lo + j]      = __float2bfloat16(left);
        nxtbf[lo + HH + j] = __float2bfloat16(right);
    }
}

// ---------------- merged: finish LSE from partials, then normalize the row ----------------
__global__ void lse_norm_kernel(float* __restrict__ logits,
                                const float* __restrict__ pmax, const float* __restrict__ psum) {
    int row = blockIdx.x;
    float m = -INFINITY, s = 0.f;
    for (int i = threadIdx.x; i < NYB; i += blockDim.x)
        lse_comb(m, s, pmax[(size_t)row * NYB + i], psum[(size_t)row * NYB + i]);
    __shared__ float sm[256], ss[256];
    sm[threadIdx.x] = m; ss[threadIdx.x] = s;
    __syncthreads();
    for (int o = 128; o > 0; o >>= 1) {
        if (threadIdx.x < o) {
            float mm = sm[threadIdx.x], sv = ss[threadIdx.x];
            lse_comb(mm, sv, sm[threadIdx.x + o], ss[threadIdx.x + o]);
            sm[threadIdx.x] = mm; ss[threadIdx.x] = sv;
        }
        __syncthreads();
    }
    float l = sm[0] + __logf(ss[0]);

    float4* p = reinterpret_cast<float4*>(logits + (size_t)row * VV);
    for (int i = threadIdx.x; i < VV / 4; i += blockDim.x) {
        float4 v = p[i];
        v.x -= l; v.y -= l; v.z -= l; v.w -= l;
        p[i] = v;
    }
}

// ---------------- launch ----------------
extern "C" void kernel_launch(void* const* d_in, const int* in_sizes, int n_in,
                              void* d_out, int out_size) {
    const float* enc   = (const float*)d_in[0];
    const float* Whh_l = (const float*)d_in[1];
    const float* bih_l = (const float*)d_in[2];
    const float* bhh_l = (const float*)d_in[3];
    const float* Whh_r = (const float*)d_in[4];
    const float* bih_r = (const float*)d_in[5];
    const float* bhh_r = (const float*)d_in[6];
    const float* W_out = (const float*)d_in[7];
    const float* b_out = (const float*)d_in[8];
    float* out = (float*)d_out;

    float *p_curA, *p_curB, *p_gh, *p_pmax, *p_psum;
    __nv_bfloat16 *p_curbf, *p_wcat, *p_wout;
    cudaGetSymbolAddress((void**)&p_curA,  g_curA);
    cudaGetSymbolAddress((void**)&p_curB,  g_curB);
    cudaGetSymbolAddress((void**)&p_gh,    g_gh);
    cudaGetSymbolAddress((void**)&p_pmax,  g_pmax);
    cudaGetSymbolAddress((void**)&p_psum,  g_psum);
    cudaGetSymbolAddress((void**)&p_curbf, g_curbf);
    cudaGetSymbolAddress((void**)&p_wcat,  g_wcat);
    cudaGetSymbolAddress((void**)&p_wout,  g_wout);

    cudaFuncSetAttribute(gemm_bf16_pipe, cudaFuncAttributeMaxDynamicSharedMemorySize, SMEM_BYTES);
    cudaFuncSetAttribute(gemm_logits,    cudaFuncAttributeMaxDynamicSharedMemorySize, L_SMEM);

    // weight conversions (every call — deterministic)
    {
        int nW = 3 * HH * HH;
        int n2 = nW / 2;
        f2bf_kernel<<<(n2 + 255) / 256, 256>>>(Whh_l, p_wcat, n2);
        f2bf_kernel<<<(n2 + 255) / 256, 256>>>(Whh_r, p_wcat + nW, n2);
        int n2o = (VV * HH) / 2;
        f2bf_kernel<<<(n2o + 255) / 256, 256>>>(W_out, p_wout, n2o);
    }

    // level 0 input
    init_kernel<<<(BB * HH) / 256, 256>>>(enc, p_curA, p_curbf);

    // tree expansion (proven mma.sync path)
    float* cur = p_curA;
    float* nxt = p_curB;
    for (int level = 0; level < DEPTHN; level++) {
        int rows = BB << level;                               // 64..1024
        dim3 grid((rows + BM - 1) / BM, GH_LD / BN);
        gemm_bf16_pipe<<<grid, 256, SMEM_BYTES>>>(p_curbf, p_wcat, p_gh, rows, GH_LD);
        gru_gate_kernel<<<rows, 256>>>(cur, p_gh, bih_l, bhh_l, bih_r, bhh_r, nxt, p_curbf);
        float* t = cur; cur = nxt; nxt = t;
    }

    // output projection with fused LSE partials
    {
        dim3 grid(MAXROWS / LBM, VV / LBN);                   // (16, 250)
        gemm_logits<<<grid, 128, L_SMEM>>>(p_curbf, p_wout, out, b_out, p_pmax, p_psum);
    }

    // log_softmax: finish LSE + normalize (merged)
    lse_norm_kernel<<<MAXROWS, 256>>>(out, p_pmax, p_psum);
}